// round 11
// baseline (speedup 1.0000x reference)
#include <cuda_runtime.h>
#include <cuda_fp16.h>
#include <math.h>
#include <stdint.h>

// ---------------- problem constants ----------------
#define BATCH   2
#define SEQLEN  512
#define DMODEL  1024
#define DINNER  2048
#define NHEADS  32
#define HEADDIM 64
#define DSTATE  128
#define DCONV   4
#define DPROJ   4384   // 2*DINNER + 2*DSTATE + NHEADS
#define NPAD    4608   // DPROJ padded to multiple of 256
#define CONVD   2304   // DINNER + 2*DSTATE
#define MROWS   (BATCH*SEQLEN)   // 1024
#define DT_OFF  (DINNER + CONVD) // 4352

// ---------------- scratch (static device memory) ----------------
__device__ float g_zx [MROWS * DPROJ];      // in_proj output  (1024 x 4384)
__device__ float g_xbc[MROWS * CONVD];      // conv+silu output
__device__ float g_yp [8][MROWS * DINNER];  // scan partial outputs (8 n-chunks)

__device__ __half g_uh [MROWS * DMODEL];
__device__ __half g_ul [MROWS * DMODEL];
__device__ __half g_wih[NPAD  * DMODEL];
__device__ __half g_ynh[MROWS * DINNER];
__device__ __half g_ynl[MROWS * DINNER];
__device__ __half g_woh[DMODEL * DINNER];

// =====================================================================
// helpers
// =====================================================================
__device__ __forceinline__ uint32_t smem_u32(const void* p) {
    uint32_t a;
    asm("{ .reg .u64 t; cvta.to.shared.u64 t, %1; cvt.u32.u64 %0, t; }"
        : "=r"(a) : "l"(p));
    return a;
}

__device__ __forceinline__ void cpa16(uint32_t dst, const void* src) {
    asm volatile("cp.async.cg.shared.global [%0], [%1], 16;"
                 :: "r"(dst), "l"(src) : "memory");
}
#define CP_COMMIT() asm volatile("cp.async.commit_group;" ::: "memory")

__device__ __forceinline__ void ldsm_x4(uint32_t addr, uint32_t& r0, uint32_t& r1,
                                        uint32_t& r2, uint32_t& r3) {
    asm volatile("ldmatrix.sync.aligned.m8n8.x4.shared.b16 {%0,%1,%2,%3}, [%4];"
                 : "=r"(r0), "=r"(r1), "=r"(r2), "=r"(r3) : "r"(addr));
}

__device__ __forceinline__ void mma_f16(float* c, const uint32_t* a,
                                        uint32_t b0, uint32_t b1) {
    asm volatile(
        "mma.sync.aligned.m16n8k16.row.col.f32.f16.f16.f32 "
        "{%0,%1,%2,%3}, {%4,%5,%6,%7}, {%8,%9}, {%0,%1,%2,%3};"
        : "+f"(c[0]), "+f"(c[1]), "+f"(c[2]), "+f"(c[3])
        : "r"(a[0]), "r"(a[1]), "r"(a[2]), "r"(a[3]), "r"(b0), "r"(b1));
}

// =====================================================================
// merged fp32 -> fp16 conversions (u hi/lo, W_in hi, W_out hi)
// =====================================================================
#define CVT_N0 (MROWS * DMODEL)              // u: 1048576
#define CVT_N1 (NPAD * DMODEL)               // W_in padded: 4718592
#define CVT_N2 (DMODEL * DINNER)             // W_out: 2097152
#define CVT_TOT (CVT_N0 + CVT_N1 + CVT_N2)

__global__ __launch_bounds__(256) void convert_all(
    const float* __restrict__ u, const float* __restrict__ W_in,
    const float* __restrict__ W_out)
{
    int i = blockIdx.x * 256 + threadIdx.x;
    if (i < CVT_N0) {
        float v = u[i];
        __half h = __float2half_rn(v);
        g_uh[i] = h;
        g_ul[i] = __float2half_rn(v - __half2float(h));
    } else if (i < CVT_N0 + CVT_N1) {
        int j = i - CVT_N0;
        float v = (j < DPROJ * DMODEL) ? W_in[j] : 0.f;
        g_wih[j] = __float2half_rn(v);
    } else if (i < CVT_TOT) {
        int j = i - CVT_N0 - CVT_N1;
        g_woh[j] = __float2half_rn(W_out[j]);
    }
}

// =====================================================================
// fp16 2-term split GEMM (NT): C[m,n] = sum_k A[m,k]*B[n,k]
//   C = Ah*Bh + Al*Bh, fp32 accum via mma.sync.m16n8k16.f16
// CTA 128x256, 8 warps (2x4), warp tile 64x64, BK=32, 3-stage cp.async.
// gridDim.z = K-splits; accum=1 -> atomicAdd (C pre-zeroed).
// =====================================================================
#define GS_ROWB 80                 // smem row stride (32 fp16 + 16B pad)
#define GS_STGB (512*GS_ROWB)      // Ah(128)+Al(128)+Bh(256) rows = 40960 B
#define GS_SMEM (3*GS_STGB)        // 3 stages: 122880 B
#define GS_AL_OFF (128*GS_ROWB)
#define GS_BH_OFF (256*GS_ROWB)

__global__ __launch_bounds__(256) void gemm_f16_2t(
    const __half* __restrict__ Ah, const __half* __restrict__ Al,
    const __half* __restrict__ Bh,
    float* __restrict__ C, int M, int N, int K, int accum)
{
    extern __shared__ char smem[];
    const uint32_t sbase = smem_u32(smem);
    const int tid = threadIdx.x;
    const int lane = tid & 31;
    const int warp = tid >> 5;
    const int wm = (warp >> 2) * 64;   // 0 or 64
    const int wn = (warp & 3) * 64;    // 0,64,128,192

    const int m0 = blockIdx.y * 128;
    const int n0 = blockIdx.x * 256;
    const int kslice = K / gridDim.z;
    const int kbeg = blockIdx.z * kslice;
    const int T = kslice / 32;

    float acc[4][8][4];
#pragma unroll
    for (int i = 0; i < 4; i++)
#pragma unroll
        for (int j = 0; j < 8; j++)
#pragma unroll
            for (int q = 0; q < 4; q++) acc[i][j][q] = 0.f;

    const __half* ptr0 = (tid < 128)
        ? Ah + (size_t)(m0 + tid) * K + kbeg
        : Al + (size_t)(m0 + tid - 128) * K + kbeg;
    const __half* ptr1 = Bh + (size_t)(n0 + tid) * K + kbeg;
    const uint32_t srow0 = sbase + tid * GS_ROWB;
    const uint32_t srow1 = sbase + (tid + 256) * GS_ROWB;

#define FILL_STAGE(STG, KOFF)                                                  \
    {                                                                          \
        uint32_t s0 = srow0 + (STG) * GS_STGB;                                 \
        uint32_t s1 = srow1 + (STG) * GS_STGB;                                 \
        _Pragma("unroll")                                                      \
        for (int sg = 0; sg < 4; sg++) {                                       \
            cpa16(s0 + sg * 16, ptr0 + (KOFF) + sg * 8);                       \
            cpa16(s1 + sg * 16, ptr1 + (KOFF) + sg * 8);                       \
        }                                                                      \
    }

    const uint32_t a_off = (uint32_t)((wm + (lane & 15)) * GS_ROWB + (lane >> 4) * 16);
    const uint32_t b_row = (uint32_t)(wn + ((lane >> 4) << 3) + (lane & 7));
    const uint32_t b_off = GS_BH_OFF + b_row * GS_ROWB + (((lane >> 3) & 1) << 4);

    FILL_STAGE(0, 0);
    CP_COMMIT();
    FILL_STAGE(1, 32);
    CP_COMMIT();

    for (int t = 0; t < T; t++) {
        asm volatile("cp.async.wait_group 1;" ::: "memory");
        __syncthreads();
        if (t + 2 < T) {
            int stg = (t + 2) % 3;
            FILL_STAGE(stg, (t + 2) * 32);
            CP_COMMIT();
        }

        const uint32_t sb = sbase + (t % 3) * GS_STGB;
#pragma unroll
        for (int ks = 0; ks < 2; ks++) {
            const uint32_t kb = ks * 32;
            uint32_t ah[4][4], al[4][4], bh[4][4];
#pragma unroll
            for (int mi = 0; mi < 4; mi++) {
                uint32_t ad = sb + a_off + mi * 16 * GS_ROWB + kb;
                ldsm_x4(ad, ah[mi][0], ah[mi][1], ah[mi][2], ah[mi][3]);
                ldsm_x4(ad + GS_AL_OFF, al[mi][0], al[mi][1], al[mi][2], al[mi][3]);
            }
#pragma unroll
            for (int bi = 0; bi < 4; bi++) {
                uint32_t bd = sb + b_off + bi * 16 * GS_ROWB + kb;
                ldsm_x4(bd, bh[bi][0], bh[bi][1], bh[bi][2], bh[bi][3]);
            }
#pragma unroll
            for (int mi = 0; mi < 4; mi++)
#pragma unroll
                for (int ni = 0; ni < 8; ni++)
                    mma_f16(acc[mi][ni], ah[mi],
                            bh[ni >> 1][(ni & 1) * 2], bh[ni >> 1][(ni & 1) * 2 + 1]);
#pragma unroll
            for (int mi = 0; mi < 4; mi++)
#pragma unroll
                for (int ni = 0; ni < 8; ni++)
                    mma_f16(acc[mi][ni], al[mi],
                            bh[ni >> 1][(ni & 1) * 2], bh[ni >> 1][(ni & 1) * 2 + 1]);
        }
    }

#pragma unroll
    for (int mi = 0; mi < 4; mi++) {
        const int r0 = m0 + wm + mi * 16 + (lane >> 2);
#pragma unroll
        for (int ni = 0; ni < 8; ni++) {
            const int c = n0 + wn + ni * 8 + (lane & 3) * 2;
            if (c < N) {
                float* p0 = C + (size_t)r0 * N + c;
                float* p1 = C + (size_t)(r0 + 8) * N + c;
                if (accum) {
                    atomicAdd(&p0[0], acc[mi][ni][0]);
                    atomicAdd(&p0[1], acc[mi][ni][1]);
                    atomicAdd(&p1[0], acc[mi][ni][2]);
                    atomicAdd(&p1[1], acc[mi][ni][3]);
                } else {
                    p0[0] = acc[mi][ni][0];
                    p0[1] = acc[mi][ni][1];
                    p1[0] = acc[mi][ni][2];
                    p1[1] = acc[mi][ni][3];
                }
            }
        }
    }
#undef FILL_STAGE
}

// =====================================================================
// Depthwise causal conv (k=4) + bias + SiLU (scalar)
// =====================================================================
__global__ __launch_bounds__(256) void conv_silu_kernel(
    const float* __restrict__ cw, const float* __restrict__ cb)
{
    int idx = blockIdx.x * blockDim.x + threadIdx.x;
    if (idx >= MROWS * CONVD) return;
    int c = idx % CONVD;
    int l = (idx / CONVD) % SEQLEN;
    int b = idx / (CONVD * SEQLEN);

    float acc = cb[c];
    const float* w = cw + c * DCONV;
#pragma unroll
    for (int j = 0; j < DCONV; j++) {
        int ls = l - (DCONV - 1) + j;
        if (ls >= 0)
            acc = fmaf(w[j], g_zx[(size_t)(b * SEQLEN + ls) * DPROJ + DINNER + c], acc);
    }
    g_xbc[idx] = acc / (1.f + expf(-acc));
}

// =====================================================================
// Sequential SSM scan, 8-way state split (16 states per chunk).
// grid = BATCH*NHEADS*8 = 512 blocks; block = 256 threads.
// thread: p = wid*8+(lane&7), sub = lane>>3 owns 4 states (float4 B/C).
// 8-step grouped prefetch; dt/dA by 8 leader threads; 2-shuffle reduce.
// =====================================================================
#define SGRP 8
__global__ __launch_bounds__(256) void ssm_scan_kernel(
    const float* __restrict__ dt_bias, const float* __restrict__ A_log,
    const float* __restrict__ Dp)
{
    const int bh    = blockIdx.x >> 3;
    const int chunk = blockIdx.x & 7;        // 16-state chunk
    const int b = bh >> 5;
    const int h = bh & 31;
    const int tid = threadIdx.x;
    const int lane = tid & 31;
    const int wid = tid >> 5;
    const int p = wid * 8 + (lane & 7);
    const int sub = lane >> 3;               // 0..3, 4 states each
    const int nloc = sub * 4;

    __shared__ float  sh[2][SGRP][96];       // [0:64) x, [64:80) B, [80:96) C
    __shared__ float2 sh_dta[2][SGRP];

    float s[4];
#pragma unroll
    for (int i = 0; i < 4; i++) s[i] = 0.f;

    const float Aval = -expf(A_log[h]);
    const float dtb  = dt_bias[h];
    const float Dv   = Dp[h];

    const float* xbase  = g_xbc + (size_t)b * SEQLEN * CONVD + h * HEADDIM;
    const float* bcbase = g_xbc + (size_t)b * SEQLEN * CONVD + DINNER;
    const float* dtbase = g_zx + (size_t)b * SEQLEN * DPROJ + DT_OFF + h;

    // loader mapping: f_idx<64 -> x, <80 -> B chunk, <96 -> C chunk, else idle
    const int f_idx = tid & 127;
    const int f_s   = tid >> 7;              // covers steps f_s, f_s+2, +4, +6
    const bool f_act = f_idx < 96;
    const float* colptr = xbase;             // safe default
    if (f_idx < 64)       colptr = xbase + f_idx;
    else if (f_idx < 80)  colptr = bcbase + chunk * 16 + (f_idx - 64);
    else if (f_idx < 96)  colptr = bcbase + 128 + chunk * 16 + (f_idx - 80);

    float pre[4];
#pragma unroll
    for (int q = 0; q < 4; q++)
        pre[q] = f_act ? colptr[(size_t)(f_s + 2 * q) * CONVD] : 0.f;
    float predt = (tid < SGRP) ? dtbase[(size_t)tid * DPROJ] : 0.f;

    float* ybase = g_yp[chunk] + (size_t)b * SEQLEN * DINNER + h * HEADDIM + p;

    for (int g = 0; g < SEQLEN / SGRP; g++) {
        const int buf = g & 1;
        if (f_act) {
#pragma unroll
            for (int q = 0; q < 4; q++)
                sh[buf][f_s + 2 * q][f_idx] = pre[q];
        }
        if (tid < SGRP) {
            const float dtr = predt + dtb;
            const float dtv = (dtr > 20.f) ? dtr : log1pf(expf(dtr));
            sh_dta[buf][tid] = make_float2(dtv, expf(dtv * Aval));
        }
        __syncthreads();

        if (g + 1 < SEQLEN / SGRP) {
            const size_t l0 = (size_t)(g + 1) * SGRP;
            if (f_act) {
#pragma unroll
                for (int q = 0; q < 4; q++)
                    pre[q] = colptr[(l0 + f_s + 2 * q) * CONVD];
            }
            if (tid < SGRP) predt = dtbase[(l0 + tid) * DPROJ];
        }

#pragma unroll
        for (int q = 0; q < SGRP; q++) {
            const float2 dta = sh_dta[buf][q];
            const float xv = sh[buf][q][p];
            const float coef = dta.x * xv;
            const float dA = dta.y;
            const float4 B = *reinterpret_cast<const float4*>(&sh[buf][q][64 + nloc]);
            const float4 C = *reinterpret_cast<const float4*>(&sh[buf][q][80 + nloc]);

            s[0] = fmaf(s[0], dA, coef * B.x);
            s[1] = fmaf(s[1], dA, coef * B.y);
            float acc0 = s[0] * C.x;
            float acc1 = s[1] * C.y;
            s[2] = fmaf(s[2], dA, coef * B.z);
            s[3] = fmaf(s[3], dA, coef * B.w);
            acc0 = fmaf(s[2], C.z, acc0);
            acc1 = fmaf(s[3], C.w, acc1);

            float acc = acc0 + acc1;
            acc += __shfl_xor_sync(0xffffffffu, acc, 8);
            acc += __shfl_xor_sync(0xffffffffu, acc, 16);
            if (sub == 0) {
                if (chunk == 0) acc = fmaf(Dv, xv, acc);
                ybase[(size_t)(g * SGRP + q) * DINNER] = acc;
            }
        }
    }
}

// =====================================================================
// Gated RMSNorm (sums 8 scan partials) -> writes fp16 hi/lo for out_proj
// =====================================================================
__global__ __launch_bounds__(256) void gated_norm_kernel(
    const float* __restrict__ nw)
{
    const int row = blockIdx.x;
    const int tid = threadIdx.x;
    __shared__ float red[256];

    float vals[8];
    float ss = 0.f;
#pragma unroll
    for (int i = 0; i < 8; i++) {
        int c = tid + i * 256;
        size_t idx = (size_t)row * DINNER + c;
        float z = g_zx[(size_t)row * DPROJ + c];
        float yv = 0.f;
#pragma unroll
        for (int k = 0; k < 8; k++) yv += g_yp[k][idx];
        float g = yv * (z / (1.f + expf(-z)));
        vals[i] = g;
        ss = fmaf(g, g, ss);
    }
    red[tid] = ss;
    __syncthreads();
#pragma unroll
    for (int stride = 128; stride >= 32; stride >>= 1) {
        if (tid < stride) red[tid] += red[tid + stride];
        __syncthreads();
    }
    if (tid < 32) {
        float v = red[tid];
#pragma unroll
        for (int o = 16; o > 0; o >>= 1)
            v += __shfl_down_sync(0xffffffffu, v, o);
        if (tid == 0) red[0] = v;
    }
    __syncthreads();
    const float scale = rsqrtf(red[0] / (float)DINNER + 1e-5f);
#pragma unroll
    for (int i = 0; i < 8; i++) {
        int c = tid + i * 256;
        size_t idx = (size_t)row * DINNER + c;
        float v = vals[i] * scale * nw[c];
        __half h = __float2half_rn(v);
        g_ynh[idx] = h;
        g_ynl[idx] = __float2half_rn(v - __half2float(h));
    }
}

// =====================================================================
// launch
// =====================================================================
extern "C" void kernel_launch(void* const* d_in, const int* in_sizes, int n_in,
                              void* d_out, int out_size)
{
    const float* u       = (const float*)d_in[0];
    const float* W_in    = (const float*)d_in[1];
    const float* conv_w  = (const float*)d_in[2];
    const float* conv_b  = (const float*)d_in[3];
    const float* dt_bias = (const float*)d_in[4];
    const float* A_log   = (const float*)d_in[5];
    const float* D_param = (const float*)d_in[6];
    const float* norm_w  = (const float*)d_in[7];
    const float* W_out   = (const float*)d_in[8];
    float* out = (float*)d_out;

    float* zx;
    cudaGetSymbolAddress((void**)&zx, g_zx);
    __half *uh, *ul, *wih, *ynh, *ynl, *woh;
    cudaGetSymbolAddress((void**)&uh,  g_uh);
    cudaGetSymbolAddress((void**)&ul,  g_ul);
    cudaGetSymbolAddress((void**)&wih, g_wih);
    cudaGetSymbolAddress((void**)&ynh, g_ynh);
    cudaGetSymbolAddress((void**)&ynl, g_ynl);
    cudaGetSymbolAddress((void**)&woh, g_woh);

    cudaFuncSetAttribute(gemm_f16_2t,
                         cudaFuncAttributeMaxDynamicSharedMemorySize, GS_SMEM);

    // 0) merged conversions
    convert_all<<<(CVT_TOT + 255) / 256, 256>>>(u, W_in, W_out);

    // 1) in_proj: (M=1024, N=4384 (pad 4608), K=1024) -- 18x8 = 144 CTAs
    {
        dim3 grid(NPAD / 256, MROWS / 128, 1);
        gemm_f16_2t<<<grid, 256, GS_SMEM>>>(uh, ul, wih, zx,
                                            MROWS, DPROJ, DMODEL, 0);
    }

    // 2) depthwise conv + silu (scalar)
    {
        int total = MROWS * CONVD;
        conv_silu_kernel<<<(total + 255) / 256, 256>>>(conv_w, conv_b);
    }

    // 3) SSM scan (8-way state split, 8-step groups) -- 512 blocks
    ssm_scan_kernel<<<BATCH * NHEADS * 8, 256>>>(dt_bias, A_log, D_param);

    // 4) gated RMSNorm (sums 8 partials, emits fp16 hi/lo)
    gated_norm_kernel<<<MROWS, 256>>>(norm_w);

    // 5) out_proj: (M=1024, N=1024, K=2048), split-K=4 -- 4x8x4 = 128 CTAs
    cudaMemsetAsync(out, 0, (size_t)out_size * sizeof(float));
    {
        dim3 grid(DMODEL / 256, MROWS / 128, 4);
        gemm_f16_2t<<<grid, 256, GS_SMEM>>>(ynh, ynl, woh, out,
                                            MROWS, DMODEL, DINNER, 1);
    }
}

// round 12
// speedup vs baseline: 1.0516x; 1.0516x over previous
#include <cuda_runtime.h>
#include <cuda_fp16.h>
#include <math.h>
#include <stdint.h>

// ---------------- problem constants ----------------
#define BATCH   2
#define SEQLEN  512
#define DMODEL  1024
#define DINNER  2048
#define NHEADS  32
#define HEADDIM 64
#define DSTATE  128
#define DCONV   4
#define DPROJ   4384   // 2*DINNER + 2*DSTATE + NHEADS
#define NPAD    4608   // DPROJ padded to multiple of 256
#define CONVD   2304   // DINNER + 2*DSTATE
#define MROWS   (BATCH*SEQLEN)   // 1024
#define DT_OFF  (DINNER + CONVD) // 4352

// ---------------- scratch (static device memory) ----------------
__device__ float g_zx [MROWS * DPROJ];      // in_proj output  (1024 x 4384)
__device__ float g_xbc[MROWS * CONVD];      // conv+silu output
__device__ float g_yp [8][MROWS * DINNER];  // scan partial outputs (8 n-chunks)

__device__ __half g_uh [MROWS * DMODEL];
__device__ __half g_ul [MROWS * DMODEL];
__device__ __half g_wih[NPAD  * DMODEL];
__device__ __half g_ynh[MROWS * DINNER];
__device__ __half g_ynl[MROWS * DINNER];
__device__ __half g_woh[DMODEL * DINNER];

// =====================================================================
// helpers
// =====================================================================
__device__ __forceinline__ uint32_t smem_u32(const void* p) {
    uint32_t a;
    asm("{ .reg .u64 t; cvta.to.shared.u64 t, %1; cvt.u32.u64 %0, t; }"
        : "=r"(a) : "l"(p));
    return a;
}

__device__ __forceinline__ void cpa16(uint32_t dst, const void* src) {
    asm volatile("cp.async.cg.shared.global [%0], [%1], 16;"
                 :: "r"(dst), "l"(src) : "memory");
}
#define CP_COMMIT() asm volatile("cp.async.commit_group;" ::: "memory")

__device__ __forceinline__ void ldsm_x4(uint32_t addr, uint32_t& r0, uint32_t& r1,
                                        uint32_t& r2, uint32_t& r3) {
    asm volatile("ldmatrix.sync.aligned.m8n8.x4.shared.b16 {%0,%1,%2,%3}, [%4];"
                 : "=r"(r0), "=r"(r1), "=r"(r2), "=r"(r3) : "r"(addr));
}

__device__ __forceinline__ void mma_f16(float* c, const uint32_t* a,
                                        uint32_t b0, uint32_t b1) {
    asm volatile(
        "mma.sync.aligned.m16n8k16.row.col.f32.f16.f16.f32 "
        "{%0,%1,%2,%3}, {%4,%5,%6,%7}, {%8,%9}, {%0,%1,%2,%3};"
        : "+f"(c[0]), "+f"(c[1]), "+f"(c[2]), "+f"(c[3])
        : "r"(a[0]), "r"(a[1]), "r"(a[2]), "r"(a[3]), "r"(b0), "r"(b1));
}

__device__ __forceinline__ uint32_t pack_h2(float a, float b) {
    __half2 h = __floats2half2_rn(a, b);
    return *reinterpret_cast<uint32_t*>(&h);
}

// =====================================================================
// merged, vectorized fp32 -> fp16 conversions (u hi/lo, W_in hi, W_out hi)
// =====================================================================
#define CVT_N0 (MROWS * DMODEL)              // u: 1048576
#define CVT_N1 (NPAD * DMODEL)               // W_in padded: 4718592
#define CVT_N2 (DMODEL * DINNER)             // W_out: 2097152
#define CVT_TOT (CVT_N0 + CVT_N1 + CVT_N2)

__global__ __launch_bounds__(256) void convert_all(
    const float* __restrict__ u, const float* __restrict__ W_in,
    const float* __restrict__ W_out)
{
    int i = (blockIdx.x * 256 + threadIdx.x) * 4;
    if (i < CVT_N0) {
        float4 v = *reinterpret_cast<const float4*>(&u[i]);
        float hx = __half2float(__float2half_rn(v.x));
        float hy = __half2float(__float2half_rn(v.y));
        float hz = __half2float(__float2half_rn(v.z));
        float hw = __half2float(__float2half_rn(v.w));
        *reinterpret_cast<uint2*>(&g_uh[i]) =
            make_uint2(pack_h2(v.x, v.y), pack_h2(v.z, v.w));
        *reinterpret_cast<uint2*>(&g_ul[i]) =
            make_uint2(pack_h2(v.x - hx, v.y - hy), pack_h2(v.z - hz, v.w - hw));
    } else if (i < CVT_N0 + CVT_N1) {
        int j = i - CVT_N0;
        float4 v = make_float4(0.f, 0.f, 0.f, 0.f);
        if (j < DPROJ * DMODEL)  // boundary is float4-aligned
            v = *reinterpret_cast<const float4*>(&W_in[j]);
        *reinterpret_cast<uint2*>(&g_wih[j]) =
            make_uint2(pack_h2(v.x, v.y), pack_h2(v.z, v.w));
    } else if (i < CVT_TOT) {
        int j = i - CVT_N0 - CVT_N1;
        float4 v = *reinterpret_cast<const float4*>(&W_out[j]);
        *reinterpret_cast<uint2*>(&g_woh[j]) =
            make_uint2(pack_h2(v.x, v.y), pack_h2(v.z, v.w));
    }
}

// =====================================================================
// fp16 2-term split GEMM (NT): C[m,n] = sum_k A[m,k]*B[n,k]
//   C = Ah*Bh + Al*Bh, fp32 accum via mma.sync.m16n8k16.f16
// CTA 128x256, 8 warps (2x4), warp tile 64x64, BK=32, 3-stage cp.async.
// gridDim.z = K-splits; accum=1 -> atomicAdd (C pre-zeroed).
// =====================================================================
#define GS_ROWB 80                 // smem row stride (32 fp16 + 16B pad)
#define GS_STGB (512*GS_ROWB)      // Ah(128)+Al(128)+Bh(256) rows = 40960 B
#define GS_SMEM (3*GS_STGB)        // 3 stages: 122880 B
#define GS_AL_OFF (128*GS_ROWB)
#define GS_BH_OFF (256*GS_ROWB)

__global__ __launch_bounds__(256) void gemm_f16_2t(
    const __half* __restrict__ Ah, const __half* __restrict__ Al,
    const __half* __restrict__ Bh,
    float* __restrict__ C, int M, int N, int K, int accum)
{
    extern __shared__ char smem[];
    const uint32_t sbase = smem_u32(smem);
    const int tid = threadIdx.x;
    const int lane = tid & 31;
    const int warp = tid >> 5;
    const int wm = (warp >> 2) * 64;   // 0 or 64
    const int wn = (warp & 3) * 64;    // 0,64,128,192

    const int m0 = blockIdx.y * 128;
    const int n0 = blockIdx.x * 256;
    const int kslice = K / gridDim.z;
    const int kbeg = blockIdx.z * kslice;
    const int T = kslice / 32;

    float acc[4][8][4];
#pragma unroll
    for (int i = 0; i < 4; i++)
#pragma unroll
        for (int j = 0; j < 8; j++)
#pragma unroll
            for (int q = 0; q < 4; q++) acc[i][j][q] = 0.f;

    const __half* ptr0 = (tid < 128)
        ? Ah + (size_t)(m0 + tid) * K + kbeg
        : Al + (size_t)(m0 + tid - 128) * K + kbeg;
    const __half* ptr1 = Bh + (size_t)(n0 + tid) * K + kbeg;
    const uint32_t srow0 = sbase + tid * GS_ROWB;
    const uint32_t srow1 = sbase + (tid + 256) * GS_ROWB;

#define FILL_STAGE(STG, KOFF)                                                  \
    {                                                                          \
        uint32_t s0 = srow0 + (STG) * GS_STGB;                                 \
        uint32_t s1 = srow1 + (STG) * GS_STGB;                                 \
        _Pragma("unroll")                                                      \
        for (int sg = 0; sg < 4; sg++) {                                       \
            cpa16(s0 + sg * 16, ptr0 + (KOFF) + sg * 8);                       \
            cpa16(s1 + sg * 16, ptr1 + (KOFF) + sg * 8);                       \
        }                                                                      \
    }

    const uint32_t a_off = (uint32_t)((wm + (lane & 15)) * GS_ROWB + (lane >> 4) * 16);
    const uint32_t b_row = (uint32_t)(wn + ((lane >> 4) << 3) + (lane & 7));
    const uint32_t b_off = GS_BH_OFF + b_row * GS_ROWB + (((lane >> 3) & 1) << 4);

    FILL_STAGE(0, 0);
    CP_COMMIT();
    FILL_STAGE(1, 32);
    CP_COMMIT();

    for (int t = 0; t < T; t++) {
        asm volatile("cp.async.wait_group 1;" ::: "memory");
        __syncthreads();
        if (t + 2 < T) {
            int stg = (t + 2) % 3;
            FILL_STAGE(stg, (t + 2) * 32);
            CP_COMMIT();
        }

        const uint32_t sb = sbase + (t % 3) * GS_STGB;
#pragma unroll
        for (int ks = 0; ks < 2; ks++) {
            const uint32_t kb = ks * 32;
            uint32_t ah[4][4], al[4][4], bh[4][4];
#pragma unroll
            for (int mi = 0; mi < 4; mi++) {
                uint32_t ad = sb + a_off + mi * 16 * GS_ROWB + kb;
                ldsm_x4(ad, ah[mi][0], ah[mi][1], ah[mi][2], ah[mi][3]);
                ldsm_x4(ad + GS_AL_OFF, al[mi][0], al[mi][1], al[mi][2], al[mi][3]);
            }
#pragma unroll
            for (int bi = 0; bi < 4; bi++) {
                uint32_t bd = sb + b_off + bi * 16 * GS_ROWB + kb;
                ldsm_x4(bd, bh[bi][0], bh[bi][1], bh[bi][2], bh[bi][3]);
            }
#pragma unroll
            for (int mi = 0; mi < 4; mi++)
#pragma unroll
                for (int ni = 0; ni < 8; ni++)
                    mma_f16(acc[mi][ni], ah[mi],
                            bh[ni >> 1][(ni & 1) * 2], bh[ni >> 1][(ni & 1) * 2 + 1]);
#pragma unroll
            for (int mi = 0; mi < 4; mi++)
#pragma unroll
                for (int ni = 0; ni < 8; ni++)
                    mma_f16(acc[mi][ni], al[mi],
                            bh[ni >> 1][(ni & 1) * 2], bh[ni >> 1][(ni & 1) * 2 + 1]);
        }
    }

#pragma unroll
    for (int mi = 0; mi < 4; mi++) {
        const int r0 = m0 + wm + mi * 16 + (lane >> 2);
#pragma unroll
        for (int ni = 0; ni < 8; ni++) {
            const int c = n0 + wn + ni * 8 + (lane & 3) * 2;
            if (c < N) {
                float* p0 = C + (size_t)r0 * N + c;
                float* p1 = C + (size_t)(r0 + 8) * N + c;
                if (accum) {
                    atomicAdd(&p0[0], acc[mi][ni][0]);
                    atomicAdd(&p0[1], acc[mi][ni][1]);
                    atomicAdd(&p1[0], acc[mi][ni][2]);
                    atomicAdd(&p1[1], acc[mi][ni][3]);
                } else {
                    p0[0] = acc[mi][ni][0];
                    p0[1] = acc[mi][ni][1];
                    p1[0] = acc[mi][ni][2];
                    p1[1] = acc[mi][ni][3];
                }
            }
        }
    }
#undef FILL_STAGE
}

// =====================================================================
// Depthwise causal conv (k=4) + bias + SiLU (scalar)
// =====================================================================
__global__ __launch_bounds__(256) void conv_silu_kernel(
    const float* __restrict__ cw, const float* __restrict__ cb)
{
    int idx = blockIdx.x * blockDim.x + threadIdx.x;
    if (idx >= MROWS * CONVD) return;
    int c = idx % CONVD;
    int l = (idx / CONVD) % SEQLEN;
    int b = idx / (CONVD * SEQLEN);

    float acc = cb[c];
    const float* w = cw + c * DCONV;
#pragma unroll
    for (int j = 0; j < DCONV; j++) {
        int ls = l - (DCONV - 1) + j;
        if (ls >= 0)
            acc = fmaf(w[j], g_zx[(size_t)(b * SEQLEN + ls) * DPROJ + DINNER + c], acc);
    }
    g_xbc[idx] = acc / (1.f + expf(-acc));
}

// =====================================================================
// Sequential SSM scan, 8-way state split, f32x2 packed math.
// grid = BATCH*NHEADS*8 = 512 blocks; block = 256 threads.
// thread: p = wid*8+(lane&7), sub = lane>>3 owns 4 states (2 f32x2 pairs).
// 8-step grouped prefetch; dt/dA by 8 leader threads; 2-shuffle reduce.
// =====================================================================
#define SGRP 8
__global__ __launch_bounds__(256) void ssm_scan_kernel(
    const float* __restrict__ dt_bias, const float* __restrict__ A_log,
    const float* __restrict__ Dp)
{
    const int bh    = blockIdx.x >> 3;
    const int chunk = blockIdx.x & 7;        // 16-state chunk
    const int b = bh >> 5;
    const int h = bh & 31;
    const int tid = threadIdx.x;
    const int lane = tid & 31;
    const int wid = tid >> 5;
    const int p = wid * 8 + (lane & 7);
    const int sub = lane >> 3;               // 0..3, 4 states each
    const int nloc = sub * 4;

    __shared__ __align__(16) float sh[2][SGRP][96];  // x(64) | B(16) | C(16)
    __shared__ float2 sh_dta[2][SGRP];

    unsigned long long s01 = 0ULL, s23 = 0ULL;

    const float Aval = -expf(A_log[h]);
    const float dtb  = dt_bias[h];
    const float Dv   = Dp[h];

    const float* xbase  = g_xbc + (size_t)b * SEQLEN * CONVD + h * HEADDIM;
    const float* bcbase = g_xbc + (size_t)b * SEQLEN * CONVD + DINNER;
    const float* dtbase = g_zx + (size_t)b * SEQLEN * DPROJ + DT_OFF + h;

    // loader mapping: f_idx<64 -> x, <80 -> B chunk, <96 -> C chunk, else idle
    const int f_idx = tid & 127;
    const int f_s   = tid >> 7;              // covers steps f_s, f_s+2, +4, +6
    const bool f_act = f_idx < 96;
    const float* colptr = xbase;             // safe default
    if (f_idx < 64)       colptr = xbase + f_idx;
    else if (f_idx < 80)  colptr = bcbase + chunk * 16 + (f_idx - 64);
    else if (f_idx < 96)  colptr = bcbase + 128 + chunk * 16 + (f_idx - 80);

    float pre[4];
#pragma unroll
    for (int q = 0; q < 4; q++)
        pre[q] = f_act ? colptr[(size_t)(f_s + 2 * q) * CONVD] : 0.f;
    float predt = (tid < SGRP) ? dtbase[(size_t)tid * DPROJ] : 0.f;

    float* ybase = g_yp[chunk] + (size_t)b * SEQLEN * DINNER + h * HEADDIM + p;

    for (int g = 0; g < SEQLEN / SGRP; g++) {
        const int buf = g & 1;
        if (f_act) {
#pragma unroll
            for (int q = 0; q < 4; q++)
                sh[buf][f_s + 2 * q][f_idx] = pre[q];
        }
        if (tid < SGRP) {
            const float dtr = predt + dtb;
            const float dtv = (dtr > 20.f) ? dtr : log1pf(expf(dtr));
            sh_dta[buf][tid] = make_float2(dtv, expf(dtv * Aval));
        }
        __syncthreads();

        if (g + 1 < SEQLEN / SGRP) {
            const size_t l0 = (size_t)(g + 1) * SGRP;
            if (f_act) {
#pragma unroll
                for (int q = 0; q < 4; q++)
                    pre[q] = colptr[(l0 + f_s + 2 * q) * CONVD];
            }
            if (tid < SGRP) predt = dtbase[(l0 + tid) * DPROJ];
        }

#pragma unroll
        for (int q = 0; q < SGRP; q++) {
            const float2 dta = sh_dta[buf][q];
            const float xv = sh[buf][q][p];
            const float coef = dta.x * xv;

            unsigned long long coef2, dA2;
            asm("mov.b64 %0, {%1, %1};" : "=l"(coef2) : "f"(coef));
            asm("mov.b64 %0, {%1, %1};" : "=l"(dA2) : "f"(dta.y));

            const ulonglong2 Bp = *reinterpret_cast<const ulonglong2*>(
                &sh[buf][q][64 + nloc]);
            const ulonglong2 Cp = *reinterpret_cast<const ulonglong2*>(
                &sh[buf][q][80 + nloc]);

            unsigned long long t0, t1, acc2;
            asm("mul.rn.f32x2 %0, %1, %2;" : "=l"(t0) : "l"(coef2), "l"(Bp.x));
            asm("mul.rn.f32x2 %0, %1, %2;" : "=l"(t1) : "l"(coef2), "l"(Bp.y));
            asm("fma.rn.f32x2 %0, %0, %1, %2;" : "+l"(s01) : "l"(dA2), "l"(t0));
            asm("fma.rn.f32x2 %0, %0, %1, %2;" : "+l"(s23) : "l"(dA2), "l"(t1));
            asm("mul.rn.f32x2 %0, %1, %2;" : "=l"(acc2) : "l"(s01), "l"(Cp.x));
            asm("fma.rn.f32x2 %0, %1, %2, %0;" : "+l"(acc2) : "l"(s23), "l"(Cp.y));

            float alo, ahi;
            asm("mov.b64 {%0, %1}, %2;" : "=f"(alo), "=f"(ahi) : "l"(acc2));
            float acc = alo + ahi;
            acc += __shfl_xor_sync(0xffffffffu, acc, 8);
            acc += __shfl_xor_sync(0xffffffffu, acc, 16);
            if (sub == 0) {
                if (chunk == 0) acc = fmaf(Dv, xv, acc);
                ybase[(size_t)(g * SGRP + q) * DINNER] = acc;
            }
        }
    }
}

// =====================================================================
// Gated RMSNorm (sums 8 scan partials, float4 loads) -> fp16 hi/lo
// =====================================================================
__global__ __launch_bounds__(256) void gated_norm_kernel(
    const float* __restrict__ nw)
{
    const int row = blockIdx.x;
    const int tid = threadIdx.x;
    const int c0 = tid * 8;
    __shared__ float red[256];

    const size_t base = (size_t)row * DINNER + c0;
    float4 v0 = make_float4(0.f, 0.f, 0.f, 0.f);
    float4 v1 = v0;
#pragma unroll
    for (int k = 0; k < 8; k++) {
        float4 a = *reinterpret_cast<const float4*>(&g_yp[k][base]);
        float4 c = *reinterpret_cast<const float4*>(&g_yp[k][base + 4]);
        v0.x += a.x; v0.y += a.y; v0.z += a.z; v0.w += a.w;
        v1.x += c.x; v1.y += c.y; v1.z += c.z; v1.w += c.w;
    }
    const float4 z0 = *reinterpret_cast<const float4*>(
        &g_zx[(size_t)row * DPROJ + c0]);
    const float4 z1 = *reinterpret_cast<const float4*>(
        &g_zx[(size_t)row * DPROJ + c0 + 4]);

    float vals[8];
    vals[0] = v0.x * (z0.x / (1.f + expf(-z0.x)));
    vals[1] = v0.y * (z0.y / (1.f + expf(-z0.y)));
    vals[2] = v0.z * (z0.z / (1.f + expf(-z0.z)));
    vals[3] = v0.w * (z0.w / (1.f + expf(-z0.w)));
    vals[4] = v1.x * (z1.x / (1.f + expf(-z1.x)));
    vals[5] = v1.y * (z1.y / (1.f + expf(-z1.y)));
    vals[6] = v1.z * (z1.z / (1.f + expf(-z1.z)));
    vals[7] = v1.w * (z1.w / (1.f + expf(-z1.w)));

    float ss = 0.f;
#pragma unroll
    for (int i = 0; i < 8; i++) ss = fmaf(vals[i], vals[i], ss);

    red[tid] = ss;
    __syncthreads();
#pragma unroll
    for (int stride = 128; stride >= 32; stride >>= 1) {
        if (tid < stride) red[tid] += red[tid + stride];
        __syncthreads();
    }
    if (tid < 32) {
        float v = red[tid];
#pragma unroll
        for (int o = 16; o > 0; o >>= 1)
            v += __shfl_down_sync(0xffffffffu, v, o);
        if (tid == 0) red[0] = v;
    }
    __syncthreads();
    const float scale = rsqrtf(red[0] / (float)DINNER + 1e-5f);

    const float4 w0 = *reinterpret_cast<const float4*>(&nw[c0]);
    const float4 w1 = *reinterpret_cast<const float4*>(&nw[c0 + 4]);
    float o[8];
    o[0] = vals[0] * scale * w0.x;  o[1] = vals[1] * scale * w0.y;
    o[2] = vals[2] * scale * w0.z;  o[3] = vals[3] * scale * w0.w;
    o[4] = vals[4] * scale * w1.x;  o[5] = vals[5] * scale * w1.y;
    o[6] = vals[6] * scale * w1.z;  o[7] = vals[7] * scale * w1.w;

    uint4 hpack, lpack;
    float hh[8];
#pragma unroll
    for (int i = 0; i < 8; i++) hh[i] = __half2float(__float2half_rn(o[i]));
    hpack.x = pack_h2(o[0], o[1]);  hpack.y = pack_h2(o[2], o[3]);
    hpack.z = pack_h2(o[4], o[5]);  hpack.w = pack_h2(o[6], o[7]);
    lpack.x = pack_h2(o[0] - hh[0], o[1] - hh[1]);
    lpack.y = pack_h2(o[2] - hh[2], o[3] - hh[3]);
    lpack.z = pack_h2(o[4] - hh[4], o[5] - hh[5]);
    lpack.w = pack_h2(o[6] - hh[6], o[7] - hh[7]);
    *reinterpret_cast<uint4*>(&g_ynh[base]) = hpack;
    *reinterpret_cast<uint4*>(&g_ynl[base]) = lpack;
}

// =====================================================================
// launch
// =====================================================================
extern "C" void kernel_launch(void* const* d_in, const int* in_sizes, int n_in,
                              void* d_out, int out_size)
{
    const float* u       = (const float*)d_in[0];
    const float* W_in    = (const float*)d_in[1];
    const float* conv_w  = (const float*)d_in[2];
    const float* conv_b  = (const float*)d_in[3];
    const float* dt_bias = (const float*)d_in[4];
    const float* A_log   = (const float*)d_in[5];
    const float* D_param = (const float*)d_in[6];
    const float* norm_w  = (const float*)d_in[7];
    const float* W_out   = (const float*)d_in[8];
    float* out = (float*)d_out;

    float* zx;
    cudaGetSymbolAddress((void**)&zx, g_zx);
    __half *uh, *ul, *wih, *ynh, *ynl, *woh;
    cudaGetSymbolAddress((void**)&uh,  g_uh);
    cudaGetSymbolAddress((void**)&ul,  g_ul);
    cudaGetSymbolAddress((void**)&wih, g_wih);
    cudaGetSymbolAddress((void**)&ynh, g_ynh);
    cudaGetSymbolAddress((void**)&ynl, g_ynl);
    cudaGetSymbolAddress((void**)&woh, g_woh);

    cudaFuncSetAttribute(gemm_f16_2t,
                         cudaFuncAttributeMaxDynamicSharedMemorySize, GS_SMEM);

    // 0) merged vectorized conversions
    convert_all<<<(CVT_TOT / 4 + 255) / 256, 256>>>(u, W_in, W_out);

    // 1) in_proj: (M=1024, N=4384 (pad 4608), K=1024) -- 18x8 = 144 CTAs
    {
        dim3 grid(NPAD / 256, MROWS / 128, 1);
        gemm_f16_2t<<<grid, 256, GS_SMEM>>>(uh, ul, wih, zx,
                                            MROWS, DPROJ, DMODEL, 0);
    }

    // 2) depthwise conv + silu (scalar)
    {
        int total = MROWS * CONVD;
        conv_silu_kernel<<<(total + 255) / 256, 256>>>(conv_w, conv_b);
    }

    // 3) SSM scan (8-way state split, f32x2, 8-step groups) -- 512 blocks
    ssm_scan_kernel<<<BATCH * NHEADS * 8, 256>>>(dt_bias, A_log, D_param);

    // 4) gated RMSNorm (sums 8 partials, vectorized, emits fp16 hi/lo)
    gated_norm_kernel<<<MROWS, 256>>>(norm_w);

    // 5) out_proj: (M=1024, N=1024, K=2048), split-K=4 -- 4x8x4 = 128 CTAs
    cudaMemsetAsync(out, 0, (size_t)out_size * sizeof(float));
    {
        dim3 grid(DMODEL / 256, MROWS / 128, 4);
        gemm_f16_2t<<<grid, 256, GS_SMEM>>>(ynh, ynl, woh, out,
                                            MROWS, DMODEL, DINNER, 1);
    }
}